// round 16
// baseline (speedup 1.0000x reference)
#include <cuda_runtime.h>
#include <cuda_fp16.h>
#include <cstdint>
#include <cstddef>

// ---------------------------------------------------------------------------
// GPT-2 forward on GB300 (sm_103 base target): fp16 HMMA GEMMs
// (2-pass exact-split weights for QKV/proj, 1-pass MLP + LM head),
// split-K + atomic residual accumulation for proj/W2, BN=64 QKV tiles,
// 64-query-tile 1-pass fp16 HMMA flash attention (double-buffered K/V,
// 3 CTA/SM), single-pass LayerNorm reduction.
// B=2, M=1024, D=1024, H=16, K=64, L=4, V=50257.
// ---------------------------------------------------------------------------

#define Bn 2
#define Mseq 1024
#define Dm 1024
#define Hh 16
#define Ll 4
#define NTOK 2048
#define VPAD 50304            // 50257 padded to multiple of 128

// ------------------------------- scratch ----------------------------------
__device__ float g_x[NTOK * Dm];                      // residual (fp32)
__device__ __half g_qkv[NTOK * 3 * Dm];               // qkv (single fp16)
__device__ __half g_y[NTOK * Dm];                     // LN out (single fp16)
__device__ __half g_a[NTOK * Dm];                     // attn out (single fp16)
__device__ __half g_h[NTOK * 4 * Dm];                 // MLP hidden (single)
// transposed weights: [N][K] K-major, fp16 (hi; lo only where 2-pass)
__device__ __half g_PiTh[Ll * 3 * Dm * Dm], g_PiTl[Ll * 3 * Dm * Dm];
__device__ __half g_PoTh[Ll * Dm * Dm],     g_PoTl[Ll * Dm * Dm];
__device__ __half g_W1Th[Ll * 4 * Dm * Dm];
__device__ __half g_W2Th[Ll * 4 * Dm * Dm];
__device__ __half g_WhTh[(size_t)VPAD * Dm];

// ----------------------------- PTX helpers --------------------------------
__device__ __forceinline__ void ldsm4(uint32_t& r0, uint32_t& r1,
                                      uint32_t& r2, uint32_t& r3, uint32_t addr)
{
    asm volatile("ldmatrix.sync.aligned.m8n8.x4.shared.b16 {%0,%1,%2,%3}, [%4];"
                 : "=r"(r0), "=r"(r1), "=r"(r2), "=r"(r3) : "r"(addr));
}
__device__ __forceinline__ void ldsm4t(uint32_t& r0, uint32_t& r1,
                                       uint32_t& r2, uint32_t& r3, uint32_t addr)
{
    asm volatile("ldmatrix.sync.aligned.m8n8.x4.trans.shared.b16 {%0,%1,%2,%3}, [%4];"
                 : "=r"(r0), "=r"(r1), "=r"(r2), "=r"(r3) : "r"(addr));
}
__device__ __forceinline__ void mma16816(float* d, const uint32_t* a,
                                         uint32_t b0, uint32_t b1)
{
    asm volatile("mma.sync.aligned.m16n8k16.row.col.f32.f16.f16.f32 "
                 "{%0,%1,%2,%3}, {%4,%5,%6,%7}, {%8,%9}, {%0,%1,%2,%3};"
                 : "+f"(d[0]), "+f"(d[1]), "+f"(d[2]), "+f"(d[3])
                 : "r"(a[0]), "r"(a[1]), "r"(a[2]), "r"(a[3]), "r"(b0), "r"(b1));
}
__device__ __forceinline__ void cp16(uint32_t sdst, const void* gsrc)
{
    asm volatile("cp.async.cg.shared.global [%0], [%1], 16;"
                 :: "r"(sdst), "l"(gsrc));
}
__device__ __forceinline__ void cp_commit() {
    asm volatile("cp.async.commit_group;");
}
__device__ __forceinline__ uint32_t pack2h(float a, float b)
{
    __half2 h = __floats2half2_rn(a, b);
    return *(uint32_t*)&h;
}
__device__ __forceinline__ void split2h(float a, float b, uint32_t& hi, uint32_t& lo)
{
    __half2 h = __floats2half2_rn(a, b);
    float ra = a - __half2float(__low2half(h));
    float rb = b - __half2float(__high2half(h));
    __half2 l = __floats2half2_rn(ra, rb);
    hi = *(uint32_t*)&h;
    lo = *(uint32_t*)&l;
}

// ---------------------------------------------------------------------------
// Embedding
// ---------------------------------------------------------------------------
__global__ void embed_kernel(const int* __restrict__ tokens,
                             const float* __restrict__ emb,
                             const float* __restrict__ pos,
                             float* __restrict__ x)
{
    int idx = blockIdx.x * blockDim.x + threadIdx.x;
    int row = idx >> 8;
    int d4  = idx & 255;
    int m   = row & (Mseq - 1);
    int t   = tokens[row];
    float4 e = ((const float4*)emb)[(size_t)t * 256 + d4];
    float4 p = ((const float4*)pos)[(size_t)m * 256 + d4];
    float4 o;
    o.x = e.x + p.x; o.y = e.y + p.y; o.z = e.z + p.z; o.w = e.w + p.w;
    ((float4*)x)[idx] = o;
}

// ---------------------------------------------------------------------------
// Transpose + split: W[K,N] fp32 -> Th (+Tl) [Nrows][K] fp16.
// 64x64 tile / 256 threads; float4 loads when N%4==0, scalar fallback;
// uint4 stores. Rows >= N zeroed.
// ---------------------------------------------------------------------------
__global__ void convT_kernel(const float* __restrict__ W,
                             __half* __restrict__ Th,
                             __half* __restrict__ Tl,
                             int K, int N, size_t wstr, size_t tstr)
{
    __shared__ float t[64][65];
    W  += (size_t)blockIdx.z * wstr;
    Th += (size_t)blockIdx.z * tstr;
    if (Tl) Tl += (size_t)blockIdx.z * tstr;
    const int n0 = blockIdx.x * 64, k0 = blockIdx.y * 64;
    const int tid = threadIdx.x;
    const bool nvec = ((N & 3) == 0);

    #pragma unroll
    for (int i = 0; i < 4; i++) {
        int idx = tid + i * 256;
        int r  = idx >> 4;
        int c4 = idx & 15;
        int n  = n0 + c4 * 4;
        float4 v;
        if (nvec && n + 3 < N) {
            v = *(const float4*)&W[(size_t)(k0 + r) * N + n];
        } else {
            const float* wr = &W[(size_t)(k0 + r) * N];
            v.x = (n     < N) ? wr[n]     : 0.f;
            v.y = (n + 1 < N) ? wr[n + 1] : 0.f;
            v.z = (n + 2 < N) ? wr[n + 2] : 0.f;
            v.w = (n + 3 < N) ? wr[n + 3] : 0.f;
        }
        t[r][c4 * 4 + 0] = v.x; t[r][c4 * 4 + 1] = v.y;
        t[r][c4 * 4 + 2] = v.z; t[r][c4 * 4 + 3] = v.w;
    }
    __syncthreads();

    #pragma unroll
    for (int i = 0; i < 2; i++) {
        int e  = tid + i * 256;
        int n  = e >> 3;
        int kg = (e & 7) * 8;
        __half hh[8], ll[8];
        #pragma unroll
        for (int j = 0; j < 8; j++) {
            float v = t[kg + j][n];
            __half h = __float2half(v);
            hh[j] = h;
            ll[j] = __float2half(v - __half2float(h));
        }
        size_t o = (size_t)(n0 + n) * K + k0 + kg;
        *(uint4*)&Th[o] = *(uint4*)hh;
        if (Tl) *(uint4*)&Tl[o] = *(uint4*)ll;
    }
}

// ---------------------------------------------------------------------------
// LayerNorm -> single fp16, single-pass (sum & sumsq in one reduction)
// ---------------------------------------------------------------------------
__global__ void ln_kernel(const float* __restrict__ x,
                          __half* __restrict__ y,
                          const float* __restrict__ s, const float* __restrict__ b)
{
    __shared__ float sh1[8], sh2[8];
    __shared__ float smu, svr;
    int row = blockIdx.x, tid = threadIdx.x;
    int lane = tid & 31, wrp = tid >> 5;
    const float* xr = x + (size_t)row * Dm;
    float v[4];
    #pragma unroll
    for (int i = 0; i < 4; i++) v[i] = xr[tid + 256 * i];
    float s1 = v[0] + v[1] + v[2] + v[3];
    float s2 = v[0] * v[0] + v[1] * v[1] + v[2] * v[2] + v[3] * v[3];
    #pragma unroll
    for (int o = 16; o; o >>= 1) {
        s1 += __shfl_down_sync(0xffffffffu, s1, o);
        s2 += __shfl_down_sync(0xffffffffu, s2, o);
    }
    if (!lane) { sh1[wrp] = s1; sh2[wrp] = s2; }
    __syncthreads();
    if (tid < 32) {
        float a1 = (tid < 8) ? sh1[tid] : 0.f;
        float a2 = (tid < 8) ? sh2[tid] : 0.f;
        #pragma unroll
        for (int o = 4; o; o >>= 1) {
            a1 += __shfl_down_sync(0xffffffffu, a1, o);
            a2 += __shfl_down_sync(0xffffffffu, a2, o);
        }
        if (!tid) {
            float mu = a1 * (1.f / Dm);
            smu = mu;
            svr = a2 * (1.f / Dm) - mu * mu;
        }
    }
    __syncthreads();
    float mu = smu;
    float rs = rsqrtf(svr + 1e-5f);
    #pragma unroll
    for (int i = 0; i < 4; i++) {
        int c = tid + 256 * i;
        float val = (v[i] - mu) * rs * s[c] + b[c];
        y[(size_t)row * Dm + c] = __float2half(val);
    }
}

__device__ __forceinline__ float gelu_new(float v)
{
    float u = 0.7978845608028654f * (v + 0.044715f * v * v * v);
    return 0.5f * v * (1.f + tanhf(u));
}

// ---------------------------------------------------------------------------
// fp16 HMMA GEMM: C[M,N] (+)= A[M,K] @ (Bh[+Bl])[N,K]^T  (A single fp16)
// CTA tile 128xBN (BN in {64,128}), BK=32, 128 threads (4 warps), 2 CTA/SM.
// PASS2: Bl correction pass. ATOMIC: split-K partial accumulation via
// atomicAdd into fp32 C (residual already in place; bias added by z==0).
// ---------------------------------------------------------------------------
#define LDB 80
#define ABYTES (128 * LDB)

template <bool PASS2, int BN>
constexpr int smem_gemm() { return 2 * (ABYTES + (PASS2 ? 2 : 1) * BN * LDB); }

template <bool BIAS, bool GELU, bool OUTF32, bool OUTH, bool PASS2, bool ATOMIC,
          int BN>
__global__ __launch_bounds__(128, 2) void gemm_hmma(
    const __half* __restrict__ A,
    const __half* __restrict__ Bh, const __half* __restrict__ Bl,
    const float* __restrict__ bias,
    float* __restrict__ C, __half* __restrict__ Ch, int N, int K)
{
    constexpr int BNB  = BN * LDB;
    constexpr int STG_ = ABYTES + (PASS2 ? 2 : 1) * BNB;
    constexpr int NT   = BN / 16;
    constexpr int NG   = BN / 32;

    extern __shared__ char smem[];
    const uint32_t sb = (uint32_t)__cvta_generic_to_shared(smem);
    const int tid  = threadIdx.x;
    const int lane = tid & 31;
    const int wid  = tid >> 5;
    const int bm = blockIdx.x * 128;
    const int bn = blockIdx.y * BN;
    const int wm = (wid & 1) * 64;
    const int wn = (wid >> 1) * (BN / 2);
    const int kLen  = K / gridDim.z;
    const int kBase = blockIdx.z * kLen;

    float acc[4][NT][4];
    #pragma unroll
    for (int i = 0; i < 4; i++)
        #pragma unroll
        for (int j = 0; j < NT; j++)
            #pragma unroll
            for (int k = 0; k < 4; k++) acc[i][j][k] = 0.f;

    auto load_stage = [&](int c, int s) {
        const int kc = kBase + c * 32;
        const uint32_t st = sb + s * STG_;
        #pragma unroll
        for (int i = 0; i < 4; i++) {
            int idx = tid + i * 128;
            int r = idx >> 2, q = idx & 3;
            cp16(st + r * LDB + q * 16, A + (size_t)(bm + r) * K + kc + q * 8);
        }
        #pragma unroll
        for (int i = 0; i < BN / 32; i++) {
            int idx = tid + i * 128;
            int r = idx >> 2, q = idx & 3;
            size_t gb = (size_t)(bn + r) * K + kc + q * 8;
            uint32_t so = st + ABYTES + r * LDB + q * 16;
            cp16(so, Bh + gb);
            if (PASS2) cp16(so + BNB, Bl + gb);
        }
        cp_commit();
    };

    const int nk = kLen / 32;
    load_stage(0, 0);

    const int lr  = lane & 15;
    const int kc2 = (lane >> 4) << 3;

    for (int c = 0; c < nk; c++) {
        const int s = c & 1;
        if (c + 1 < nk) {
            load_stage(c + 1, s ^ 1);
            asm volatile("cp.async.wait_group 1;");
        } else {
            asm volatile("cp.async.wait_group 0;");
        }
        __syncthreads();

        const uint32_t st = sb + s * STG_;
        #pragma unroll
        for (int ks = 0; ks < 2; ks++) {
            const uint32_t ao = st + (wm + lr) * LDB + (ks * 16 + kc2) * 2;
            const uint32_t bo = st + ABYTES + (wn + lr) * LDB + (ks * 16 + kc2) * 2;
            uint32_t af[4][4], bh[NG][4], bl[NG][4];
            #pragma unroll
            for (int mt = 0; mt < 4; mt++)
                ldsm4(af[mt][0], af[mt][1], af[mt][2], af[mt][3], ao + mt * 16 * LDB);
            #pragma unroll
            for (int g = 0; g < NG; g++)
                ldsm4(bh[g][0], bh[g][1], bh[g][2], bh[g][3], bo + g * 16 * LDB);
            if (PASS2) {
                #pragma unroll
                for (int g = 0; g < NG; g++)
                    ldsm4(bl[g][0], bl[g][1], bl[g][2], bl[g][3],
                          bo + BNB + g * 16 * LDB);
            }

            #pragma unroll
            for (int mt = 0; mt < 4; mt++)
                #pragma unroll
                for (int nt = 0; nt < NT; nt++) {
                    int g = nt >> 1, h = nt & 1;
                    mma16816(acc[mt][nt], af[mt], bh[g][h], bh[g][2 + h]);
                    if (PASS2)
                        mma16816(acc[mt][nt], af[mt], bl[g][h], bl[g][2 + h]);
                }
        }
        __syncthreads();
    }

    const bool headN = (N & 1) != 0;
    const bool addBias = BIAS && (blockIdx.z == 0);
    #pragma unroll
    for (int mt = 0; mt < 4; mt++) {
        #pragma unroll
        for (int nt = 0; nt < NT; nt++) {
            int row0 = bm + wm + mt * 16 + (lane >> 2);
            int col  = bn + wn + nt * 8 + (lane & 3) * 2;
            #pragma unroll
            for (int half = 0; half < 2; half++) {
                int row = row0 + half * 8;
                float v0 = acc[mt][nt][half * 2];
                float v1 = acc[mt][nt][half * 2 + 1];
                if (!headN) {
                    size_t base = (size_t)row * N + col;
                    if (BIAS && !ATOMIC) { v0 += bias[col]; v1 += bias[col + 1]; }
                    if (ATOMIC && addBias) { v0 += bias ? bias[col] : 0.f;
                                             v1 += bias ? bias[col + 1] : 0.f; }
                    if (GELU) { v0 = gelu_new(v0); v1 = gelu_new(v1); }
                    if (OUTF32) {
                        float2 o; o.x = v0; o.y = v1;
                        *(float2*)&C[base] = o;
                    }
                    if (OUTH) {
                        *(uint32_t*)&Ch[base] = pack2h(v0, v1);
                    }
                    if (ATOMIC) {
                        atomicAdd(&C[base], v0);
                        atomicAdd(&C[base + 1], v1);
                    }
                } else {
                    size_t rb = (size_t)row * N;
                    if (col < N) {
                        float v = v0;
                        if (BIAS) v += bias[col];
                        C[rb + col] = v;
                    }
                    if (col + 1 < N) {
                        float v = v1;
                        if (BIAS) v += bias[col + 1];
                        C[rb + col + 1] = v;
                    }
                }
            }
        }
    }
}

// ---------------------------------------------------------------------------
// fp16 flash attention (causal), 1-pass, 64-query CTAs, double-buffered K/V,
// 3 CTAs/SM. 128 threads = 4 warps x 16 queries; fp32 softmax.
// ---------------------------------------------------------------------------
#define AROWB 144
#define QBYTES 9216
#define KVSTG  18432
#define SMEM_ATT (QBYTES + 2 * KVSTG)   // 46080

__global__ __launch_bounds__(128, 3) void attn_tc(
    const __half* __restrict__ qkv,
    __half* __restrict__ aout)
{
    extern __shared__ char smem[];
    const uint32_t sb = (uint32_t)__cvta_generic_to_shared(smem);
    const uint32_t sQ = sb;
    const int tid = threadIdx.x, lane = tid & 31, w = tid >> 5;
    const int qt = gridDim.x - 1 - blockIdx.x;     // big tiles first
    const int h = blockIdx.y, b = blockIdx.z;

    #pragma unroll
    for (int i = 0; i < 4; i++) {
        int idx = tid + i * 128;
        int r = idx >> 3, q8 = idx & 7;
        size_t g = ((size_t)(b * Mseq + qt * 64 + r)) * 3072 + h * 192 + q8 * 8;
        cp16(sQ + r * AROWB + q8 * 16, qkv + g);
    }
    cp_commit();

    auto load_kv = [&](int kt, int s) {
        const uint32_t st = sb + QBYTES + s * KVSTG;
        #pragma unroll
        for (int i = 0; i < 4; i++) {
            int idx = tid + i * 128;
            int r = idx >> 3, q8 = idx & 7;
            size_t base = ((size_t)(b * Mseq + kt * 64 + r)) * 3072 + h * 192;
            uint32_t sd = r * AROWB + q8 * 16;
            cp16(st + sd,        qkv + base + 64  + q8 * 8);
            cp16(st + 9216 + sd, qkv + base + 128 + q8 * 8);
        }
        cp_commit();
    };

    const int nkt = qt + 1;
    load_kv(0, 0);
    asm volatile("cp.async.wait_group 1;");
    __syncthreads();

    const int lr  = lane & 15;
    const int khi = (lane >> 4) << 3;

    uint32_t qf[4][4];
    #pragma unroll
    for (int kc = 0; kc < 4; kc++) {
        uint32_t ad = (w * 16 + lr) * AROWB + (kc * 16 + khi) * 2;
        ldsm4(qf[kc][0], qf[kc][1], qf[kc][2], qf[kc][3], sQ + ad);
    }

    float oacc[8][4];
    #pragma unroll
    for (int i = 0; i < 8; i++)
        #pragma unroll
        for (int j = 0; j < 4; j++) oacc[i][j] = 0.f;
    float mA = -1e30f, mB = -1e30f, lA = 0.f, lB = 0.f;

    const int rowA = qt * 64 + w * 16 + (lane >> 2);
    const int rowB = rowA + 8;

    for (int kt = 0; kt < nkt; kt++) {
        const int s = kt & 1;
        if (kt + 1 < nkt) {
            load_kv(kt + 1, s ^ 1);
            asm volatile("cp.async.wait_group 1;");
        } else {
            asm volatile("cp.async.wait_group 0;");
        }
        __syncthreads();

        const uint32_t sK = sb + QBYTES + s * KVSTG;
        const uint32_t sV = sK + 9216;

        float sacc[8][4];
        #pragma unroll
        for (int i = 0; i < 8; i++)
            #pragma unroll
            for (int j = 0; j < 4; j++) sacc[i][j] = 0.f;

        #pragma unroll
        for (int kc = 0; kc < 4; kc++) {
            uint32_t kf[4][4];
            #pragma unroll
            for (int g = 0; g < 4; g++) {
                uint32_t ad = (g * 16 + lr) * AROWB + (kc * 16 + khi) * 2;
                ldsm4(kf[g][0], kf[g][1], kf[g][2], kf[g][3], sK + ad);
            }
            #pragma unroll
            for (int nt = 0; nt < 8; nt++) {
                int g = nt >> 1, hh = nt & 1;
                mma16816(sacc[nt], qf[kc], kf[g][hh], kf[g][2 + hh]);
            }
        }

        float mxA = -1e30f, mxB = -1e30f;
        #pragma unroll
        for (int nt = 0; nt < 8; nt++) {
            int k0 = kt * 64 + nt * 8 + (lane & 3) * 2;
            float s0 = sacc[nt][0] * 0.125f;
            float s1 = sacc[nt][1] * 0.125f;
            float s2 = sacc[nt][2] * 0.125f;
            float s3 = sacc[nt][3] * 0.125f;
            if (k0     > rowA) s0 = -1e30f;
            if (k0 + 1 > rowA) s1 = -1e30f;
            if (k0     > rowB) s2 = -1e30f;
            if (k0 + 1 > rowB) s3 = -1e30f;
            sacc[nt][0] = s0; sacc[nt][1] = s1;
            sacc[nt][2] = s2; sacc[nt][3] = s3;
            mxA = fmaxf(mxA, fmaxf(s0, s1));
            mxB = fmaxf(mxB, fmaxf(s2, s3));
        }
        mxA = fmaxf(mxA, __shfl_xor_sync(0xffffffffu, mxA, 1));
        mxA = fmaxf(mxA, __shfl_xor_sync(0xffffffffu, mxA, 2));
        mxB = fmaxf(mxB, __shfl_xor_sync(0xffffffffu, mxB, 1));
        mxB = fmaxf(mxB, __shfl_xor_sync(0xffffffffu, mxB, 2));
        float mnA = fmaxf(mA, mxA), mnB = fmaxf(mB, mxB);
        float cA = __expf(mA - mnA), cB = __expf(mB - mnB);
        mA = mnA; mB = mnB;

        float sA = 0.f, sB = 0.f;
        #pragma unroll
        for (int nt = 0; nt < 8; nt++) {
            sacc[nt][0] = __expf(sacc[nt][0] - mnA);
            sacc[nt][1] = __expf(sacc[nt][1] - mnA);
            sacc[nt][2] = __expf(sacc[nt][2] - mnB);
            sacc[nt][3] = __expf(sacc[nt][3] - mnB);
            sA += sacc[nt][0] + sacc[nt][1];
            sB += sacc[nt][2] + sacc[nt][3];
        }
        sA += __shfl_xor_sync(0xffffffffu, sA, 1);
        sA += __shfl_xor_sync(0xffffffffu, sA, 2);
        sB += __shfl_xor_sync(0xffffffffu, sB, 1);
        sB += __shfl_xor_sync(0xffffffffu, sB, 2);
        lA = lA * cA + sA;
        lB = lB * cB + sB;
        #pragma unroll
        for (int nt = 0; nt < 8; nt++) {
            oacc[nt][0] *= cA; oacc[nt][1] *= cA;
            oacc[nt][2] *= cB; oacc[nt][3] *= cB;
        }

        #pragma unroll
        for (int kc = 0; kc < 4; kc++) {
            uint32_t ph[4];
            ph[0] = pack2h(sacc[2 * kc][0],     sacc[2 * kc][1]);
            ph[1] = pack2h(sacc[2 * kc][2],     sacc[2 * kc][3]);
            ph[2] = pack2h(sacc[2 * kc + 1][0], sacc[2 * kc + 1][1]);
            ph[3] = pack2h(sacc[2 * kc + 1][2], sacc[2 * kc + 1][3]);

            uint32_t vf[4][4];
            #pragma unroll
            for (int dg = 0; dg < 4; dg++) {
                uint32_t ad = (kc * 16 + (lane & 7) + ((lane >> 4) << 3)) * AROWB
                            + (dg * 16 + ((lane >> 3) & 1) * 8) * 2;
                ldsm4t(vf[dg][0], vf[dg][1], vf[dg][2], vf[dg][3], sV + ad);
            }
            #pragma unroll
            for (int nt = 0; nt < 8; nt++) {
                int dg = nt >> 1, hh = nt & 1;
                mma16816(oacc[nt], ph, vf[dg][hh], vf[dg][hh + 2]);
            }
        }
        __syncthreads();
    }

    float iA = 1.f / lA, iB = 1.f / lB;
    #pragma unroll
    for (int nt = 0; nt < 8; nt++) {
        int col = h * 64 + nt * 8 + (lane & 3) * 2;
        size_t gA = ((size_t)(b * Mseq + rowA)) * Dm + col;
        size_t gB = ((size_t)(b * Mseq + rowB)) * Dm + col;
        *(uint32_t*)&aout[gA] = pack2h(oacc[nt][0] * iA, oacc[nt][1] * iA);
        *(uint32_t*)&aout[gB] = pack2h(oacc[nt][2] * iB, oacc[nt][3] * iB);
    }
}

// ---------------------------------------------------------------------------
// Host launcher
// ---------------------------------------------------------------------------
extern "C" void kernel_launch(void* const* d_in, const int* in_sizes, int n_in,
                              void* d_out, int out_size)
{
    const int*   tokens = (const int*)  d_in[0];
    const float* emb    = (const float*)d_in[1];
    const float* pos    = (const float*)d_in[2];
    const float* ln1_s  = (const float*)d_in[3];
    const float* ln1_b  = (const float*)d_in[4];
    const float* Pi     = (const float*)d_in[5];
    const float* Po     = (const float*)d_in[6];
    const float* ln2_s  = (const float*)d_in[7];
    const float* ln2_b  = (const float*)d_in[8];
    const float* W1     = (const float*)d_in[9];
    const float* b1     = (const float*)d_in[10];
    const float* W2     = (const float*)d_in[11];
    const float* b2     = (const float*)d_in[12];
    const float* lnf_s  = (const float*)d_in[13];
    const float* lnf_b  = (const float*)d_in[14];
    const float* Wh     = (const float*)d_in[15];
    const float* bh     = (const float*)d_in[16];
    float* out = (float*)d_out;
    const int V = in_sizes[16];

    float *x;
    __half *qkv, *y, *a, *hbuf;
    __half *PiTh, *PiTl, *PoTh, *PoTl, *W1Th, *W2Th, *WhTh;
    cudaGetSymbolAddress((void**)&x,    g_x);
    cudaGetSymbolAddress((void**)&qkv,  g_qkv);
    cudaGetSymbolAddress((void**)&y,    g_y);
    cudaGetSymbolAddress((void**)&a,    g_a);
    cudaGetSymbolAddress((void**)&hbuf, g_h);
    cudaGetSymbolAddress((void**)&PiTh, g_PiTh); cudaGetSymbolAddress((void**)&PiTl, g_PiTl);
    cudaGetSymbolAddress((void**)&PoTh, g_PoTh); cudaGetSymbolAddress((void**)&PoTl, g_PoTl);
    cudaGetSymbolAddress((void**)&W1Th, g_W1Th);
    cudaGetSymbolAddress((void**)&W2Th, g_W2Th);
    cudaGetSymbolAddress((void**)&WhTh, g_WhTh);

    constexpr int SM_QKV = smem_gemm<true, 64>();
    constexpr int SM_2P  = smem_gemm<true, 128>();
    constexpr int SM_1P  = smem_gemm<false, 128>();

    cudaFuncSetAttribute(gemm_hmma<false, false, false, true,  true,  false, 64>,
                         cudaFuncAttributeMaxDynamicSharedMemorySize, SM_QKV);
    cudaFuncSetAttribute(gemm_hmma<false, false, false, false, true,  true,  128>,
                         cudaFuncAttributeMaxDynamicSharedMemorySize, SM_2P);
    cudaFuncSetAttribute(gemm_hmma<true,  true,  false, true,  false, false, 128>,
                         cudaFuncAttributeMaxDynamicSharedMemorySize, SM_1P);
    cudaFuncSetAttribute(gemm_hmma<true,  false, false, false, false, true,  128>,
                         cudaFuncAttributeMaxDynamicSharedMemorySize, SM_1P);
    cudaFuncSetAttribute(gemm_hmma<true,  false, true,  false, false, false, 128>,
                         cudaFuncAttributeMaxDynamicSharedMemorySize, SM_1P);
    cudaFuncSetAttribute(attn_tc,
                         cudaFuncAttributeMaxDynamicSharedMemorySize, SMEM_ATT);

    convT_kernel<<<dim3(48, 16, Ll), 256>>>(Pi, PiTh, PiTl, Dm, 3 * Dm,
                                            (size_t)Dm * 3 * Dm, (size_t)3 * Dm * Dm);
    convT_kernel<<<dim3(16, 16, Ll), 256>>>(Po, PoTh, PoTl, Dm, Dm,
                                            (size_t)Dm * Dm, (size_t)Dm * Dm);
    convT_kernel<<<dim3(64, 16, Ll), 256>>>(W1, W1Th, nullptr, Dm, 4 * Dm,
                                            (size_t)Dm * 4 * Dm, (size_t)4 * Dm * Dm);
    convT_kernel<<<dim3(16, 64, Ll), 256>>>(W2, W2Th, nullptr, 4 * Dm, Dm,
                                            (size_t)4 * Dm * Dm, (size_t)4 * Dm * Dm);
    convT_kernel<<<dim3(VPAD / 64, 16, 1), 256>>>(Wh, WhTh, nullptr, Dm, V, 0, 0);

    embed_kernel<<<NTOK, 256>>>(tokens, emb, pos, x);

    for (int l = 0; l < Ll; l++) {
        ln_kernel<<<NTOK, 256>>>(x, y, ln1_s + l * Dm, ln1_b + l * Dm);
        gemm_hmma<false, false, false, true, true, false, 64>
            <<<dim3(16, 48), 128, SM_QKV>>>(
            y, PiTh + (size_t)l * 3 * Dm * Dm, PiTl + (size_t)l * 3 * Dm * Dm,
            nullptr, nullptr, qkv, 3 * Dm, Dm);
        attn_tc<<<dim3(16, Hh, Bn), 128, SMEM_ATT>>>(qkv, a);
        gemm_hmma<false, false, false, false, true, true, 128>
            <<<dim3(16, 8, 2), 128, SM_2P>>>(
            a, PoTh + (size_t)l * Dm * Dm, PoTl + (size_t)l * Dm * Dm,
            nullptr, x, nullptr, Dm, Dm);
        ln_kernel<<<NTOK, 256>>>(x, y, ln2_s + l * Dm, ln2_b + l * Dm);
        gemm_hmma<true, true, false, true, false, false, 128>
            <<<dim3(16, 32), 128, SM_1P>>>(
            y, W1Th + (size_t)l * 4 * Dm * Dm, nullptr,
            b1 + (size_t)l * 4 * Dm, nullptr, hbuf, 4 * Dm, Dm);
        gemm_hmma<true, false, false, false, false, true, 128>
            <<<dim3(16, 8, 2), 128, SM_1P>>>(
            hbuf, W2Th + (size_t)l * 4 * Dm * Dm, nullptr,
            b2 + (size_t)l * Dm, x, nullptr, Dm, 4 * Dm);
    }

    ln_kernel<<<NTOK, 256>>>(x, y, lnf_s, lnf_b);
    gemm_hmma<true, false, true, false, false, false, 128>
        <<<dim3(16, VPAD / 128), 128, SM_1P>>>(
        y, WhTh, nullptr, bh, out, nullptr, V, Dm);
}

// round 17
// speedup vs baseline: 1.0795x; 1.0795x over previous
#include <cuda_runtime.h>
#include <cuda_fp16.h>
#include <cstdint>
#include <cstddef>

// ---------------------------------------------------------------------------
// GPT-2 forward on GB300 (sm_103 base target): 1-pass fp16 HMMA GEMMs
// (all weights single-rounded fp16), split-K + atomic residual accumulation
// for proj/W2, BN=64 QKV tiles, 64-query-tile 1-pass fp16 HMMA flash
// attention (double-buffered K/V, 3 CTA/SM), single-pass LayerNorm.
// B=2, M=1024, D=1024, H=16, K=64, L=4, V=50257.
// ---------------------------------------------------------------------------

#define Bn 2
#define Mseq 1024
#define Dm 1024
#define Hh 16
#define Ll 4
#define NTOK 2048
#define VPAD 50304            // 50257 padded to multiple of 128

// ------------------------------- scratch ----------------------------------
__device__ float g_x[NTOK * Dm];                      // residual (fp32)
__device__ __half g_qkv[NTOK * 3 * Dm];               // qkv (single fp16)
__device__ __half g_y[NTOK * Dm];                     // LN out (single fp16)
__device__ __half g_a[NTOK * Dm];                     // attn out (single fp16)
__device__ __half g_h[NTOK * 4 * Dm];                 // MLP hidden (single)
// transposed weights: [N][K] K-major, fp16 (single-rounded)
__device__ __half g_PiTh[Ll * 3 * Dm * Dm];
__device__ __half g_PoTh[Ll * Dm * Dm];
__device__ __half g_W1Th[Ll * 4 * Dm * Dm];
__device__ __half g_W2Th[Ll * 4 * Dm * Dm];
__device__ __half g_WhTh[(size_t)VPAD * Dm];

// ----------------------------- PTX helpers --------------------------------
__device__ __forceinline__ void ldsm4(uint32_t& r0, uint32_t& r1,
                                      uint32_t& r2, uint32_t& r3, uint32_t addr)
{
    asm volatile("ldmatrix.sync.aligned.m8n8.x4.shared.b16 {%0,%1,%2,%3}, [%4];"
                 : "=r"(r0), "=r"(r1), "=r"(r2), "=r"(r3) : "r"(addr));
}
__device__ __forceinline__ void ldsm4t(uint32_t& r0, uint32_t& r1,
                                       uint32_t& r2, uint32_t& r3, uint32_t addr)
{
    asm volatile("ldmatrix.sync.aligned.m8n8.x4.trans.shared.b16 {%0,%1,%2,%3}, [%4];"
                 : "=r"(r0), "=r"(r1), "=r"(r2), "=r"(r3) : "r"(addr));
}
__device__ __forceinline__ void mma16816(float* d, const uint32_t* a,
                                         uint32_t b0, uint32_t b1)
{
    asm volatile("mma.sync.aligned.m16n8k16.row.col.f32.f16.f16.f32 "
                 "{%0,%1,%2,%3}, {%4,%5,%6,%7}, {%8,%9}, {%0,%1,%2,%3};"
                 : "+f"(d[0]), "+f"(d[1]), "+f"(d[2]), "+f"(d[3])
                 : "r"(a[0]), "r"(a[1]), "r"(a[2]), "r"(a[3]), "r"(b0), "r"(b1));
}
__device__ __forceinline__ void cp16(uint32_t sdst, const void* gsrc)
{
    asm volatile("cp.async.cg.shared.global [%0], [%1], 16;"
                 :: "r"(sdst), "l"(gsrc));
}
__device__ __forceinline__ void cp_commit() {
    asm volatile("cp.async.commit_group;");
}
__device__ __forceinline__ uint32_t pack2h(float a, float b)
{
    __half2 h = __floats2half2_rn(a, b);
    return *(uint32_t*)&h;
}

// ---------------------------------------------------------------------------
// Embedding
// ---------------------------------------------------------------------------
__global__ void embed_kernel(const int* __restrict__ tokens,
                             const float* __restrict__ emb,
                             const float* __restrict__ pos,
                             float* __restrict__ x)
{
    int idx = blockIdx.x * blockDim.x + threadIdx.x;
    int row = idx >> 8;
    int d4  = idx & 255;
    int m   = row & (Mseq - 1);
    int t   = tokens[row];
    float4 e = ((const float4*)emb)[(size_t)t * 256 + d4];
    float4 p = ((const float4*)pos)[(size_t)m * 256 + d4];
    float4 o;
    o.x = e.x + p.x; o.y = e.y + p.y; o.z = e.z + p.z; o.w = e.w + p.w;
    ((float4*)x)[idx] = o;
}

// ---------------------------------------------------------------------------
// Transpose + convert: W[K,N] fp32 -> Th [Nrows][K] fp16 (single-rounded).
// 64x64 tile / 256 threads; float4 loads when N%4==0, scalar fallback;
// uint4 stores. Rows >= N zeroed.
// ---------------------------------------------------------------------------
__global__ void convT_kernel(const float* __restrict__ W,
                             __half* __restrict__ Th,
                             int K, int N, size_t wstr, size_t tstr)
{
    __shared__ float t[64][65];
    W  += (size_t)blockIdx.z * wstr;
    Th += (size_t)blockIdx.z * tstr;
    const int n0 = blockIdx.x * 64, k0 = blockIdx.y * 64;
    const int tid = threadIdx.x;
    const bool nvec = ((N & 3) == 0);

    #pragma unroll
    for (int i = 0; i < 4; i++) {
        int idx = tid + i * 256;
        int r  = idx >> 4;
        int c4 = idx & 15;
        int n  = n0 + c4 * 4;
        float4 v;
        if (nvec && n + 3 < N) {
            v = *(const float4*)&W[(size_t)(k0 + r) * N + n];
        } else {
            const float* wr = &W[(size_t)(k0 + r) * N];
            v.x = (n     < N) ? wr[n]     : 0.f;
            v.y = (n + 1 < N) ? wr[n + 1] : 0.f;
            v.z = (n + 2 < N) ? wr[n + 2] : 0.f;
            v.w = (n + 3 < N) ? wr[n + 3] : 0.f;
        }
        t[r][c4 * 4 + 0] = v.x; t[r][c4 * 4 + 1] = v.y;
        t[r][c4 * 4 + 2] = v.z; t[r][c4 * 4 + 3] = v.w;
    }
    __syncthreads();

    #pragma unroll
    for (int i = 0; i < 2; i++) {
        int e  = tid + i * 256;
        int n  = e >> 3;
        int kg = (e & 7) * 8;
        __half hh[8];
        #pragma unroll
        for (int j = 0; j < 8; j++)
            hh[j] = __float2half(t[kg + j][n]);
        size_t o = (size_t)(n0 + n) * K + k0 + kg;
        *(uint4*)&Th[o] = *(uint4*)hh;
    }
}

// ---------------------------------------------------------------------------
// LayerNorm -> single fp16, single-pass reduction
// ---------------------------------------------------------------------------
__global__ void ln_kernel(const float* __restrict__ x,
                          __half* __restrict__ y,
                          const float* __restrict__ s, const float* __restrict__ b)
{
    __shared__ float sh1[8], sh2[8];
    __shared__ float smu, svr;
    int row = blockIdx.x, tid = threadIdx.x;
    int lane = tid & 31, wrp = tid >> 5;
    const float* xr = x + (size_t)row * Dm;
    float v[4];
    #pragma unroll
    for (int i = 0; i < 4; i++) v[i] = xr[tid + 256 * i];
    float s1 = v[0] + v[1] + v[2] + v[3];
    float s2 = v[0] * v[0] + v[1] * v[1] + v[2] * v[2] + v[3] * v[3];
    #pragma unroll
    for (int o = 16; o; o >>= 1) {
        s1 += __shfl_down_sync(0xffffffffu, s1, o);
        s2 += __shfl_down_sync(0xffffffffu, s2, o);
    }
    if (!lane) { sh1[wrp] = s1; sh2[wrp] = s2; }
    __syncthreads();
    if (tid < 32) {
        float a1 = (tid < 8) ? sh1[tid] : 0.f;
        float a2 = (tid < 8) ? sh2[tid] : 0.f;
        #pragma unroll
        for (int o = 4; o; o >>= 1) {
            a1 += __shfl_down_sync(0xffffffffu, a1, o);
            a2 += __shfl_down_sync(0xffffffffu, a2, o);
        }
        if (!tid) {
            float mu = a1 * (1.f / Dm);
            smu = mu;
            svr = a2 * (1.f / Dm) - mu * mu;
        }
    }
    __syncthreads();
    float mu = smu;
    float rs = rsqrtf(svr + 1e-5f);
    #pragma unroll
    for (int i = 0; i < 4; i++) {
        int c = tid + 256 * i;
        float val = (v[i] - mu) * rs * s[c] + b[c];
        y[(size_t)row * Dm + c] = __float2half(val);
    }
}

__device__ __forceinline__ float gelu_new(float v)
{
    float u = 0.7978845608028654f * (v + 0.044715f * v * v * v);
    return 0.5f * v * (1.f + tanhf(u));
}

// ---------------------------------------------------------------------------
// 1-pass fp16 HMMA GEMM: C[M,N] (+)= A[M,K] @ B[N,K]^T
// CTA tile 128xBN (BN in {64,128}), BK=32, 128 threads (4 warps), 2 CTA/SM.
// ATOMIC: split-K partial accumulation via atomicAdd into fp32 C
// (residual already in place; bias added by z==0).
// ---------------------------------------------------------------------------
#define LDB 80
#define ABYTES (128 * LDB)

template <int BN>
constexpr int smem_gemm() { return 2 * (ABYTES + BN * LDB); }

template <bool BIAS, bool GELU, bool OUTF32, bool OUTH, bool ATOMIC, int BN>
__global__ __launch_bounds__(128, 2) void gemm_hmma(
    const __half* __restrict__ A, const __half* __restrict__ B,
    const float* __restrict__ bias,
    float* __restrict__ C, __half* __restrict__ Ch, int N, int K)
{
    constexpr int BNB  = BN * LDB;
    constexpr int STG_ = ABYTES + BNB;
    constexpr int NT   = BN / 16;
    constexpr int NG   = BN / 32;

    extern __shared__ char smem[];
    const uint32_t sb = (uint32_t)__cvta_generic_to_shared(smem);
    const int tid  = threadIdx.x;
    const int lane = tid & 31;
    const int wid  = tid >> 5;
    const int bm = blockIdx.x * 128;
    const int bn = blockIdx.y * BN;
    const int wm = (wid & 1) * 64;
    const int wn = (wid >> 1) * (BN / 2);
    const int kLen  = K / gridDim.z;
    const int kBase = blockIdx.z * kLen;

    float acc[4][NT][4];
    #pragma unroll
    for (int i = 0; i < 4; i++)
        #pragma unroll
        for (int j = 0; j < NT; j++)
            #pragma unroll
            for (int k = 0; k < 4; k++) acc[i][j][k] = 0.f;

    auto load_stage = [&](int c, int s) {
        const int kc = kBase + c * 32;
        const uint32_t st = sb + s * STG_;
        #pragma unroll
        for (int i = 0; i < 4; i++) {
            int idx = tid + i * 128;
            int r = idx >> 2, q = idx & 3;
            cp16(st + r * LDB + q * 16, A + (size_t)(bm + r) * K + kc + q * 8);
        }
        #pragma unroll
        for (int i = 0; i < BN / 32; i++) {
            int idx = tid + i * 128;
            int r = idx >> 2, q = idx & 3;
            cp16(st + ABYTES + r * LDB + q * 16,
                 B + (size_t)(bn + r) * K + kc + q * 8);
        }
        cp_commit();
    };

    const int nk = kLen / 32;
    load_stage(0, 0);

    const int lr  = lane & 15;
    const int kc2 = (lane >> 4) << 3;

    for (int c = 0; c < nk; c++) {
        const int s = c & 1;
        if (c + 1 < nk) {
            load_stage(c + 1, s ^ 1);
            asm volatile("cp.async.wait_group 1;");
        } else {
            asm volatile("cp.async.wait_group 0;");
        }
        __syncthreads();

        const uint32_t st = sb + s * STG_;
        #pragma unroll
        for (int ks = 0; ks < 2; ks++) {
            const uint32_t ao = st + (wm + lr) * LDB + (ks * 16 + kc2) * 2;
            const uint32_t bo = st + ABYTES + (wn + lr) * LDB + (ks * 16 + kc2) * 2;
            uint32_t af[4][4], bf[NG][4];
            #pragma unroll
            for (int mt = 0; mt < 4; mt++)
                ldsm4(af[mt][0], af[mt][1], af[mt][2], af[mt][3], ao + mt * 16 * LDB);
            #pragma unroll
            for (int g = 0; g < NG; g++)
                ldsm4(bf[g][0], bf[g][1], bf[g][2], bf[g][3], bo + g * 16 * LDB);

            #pragma unroll
            for (int mt = 0; mt < 4; mt++)
                #pragma unroll
                for (int nt = 0; nt < NT; nt++) {
                    int g = nt >> 1, h = nt & 1;
                    mma16816(acc[mt][nt], af[mt], bf[g][h], bf[g][2 + h]);
                }
        }
        __syncthreads();
    }

    const bool headN = (N & 1) != 0;
    const bool addBias = BIAS && (blockIdx.z == 0);
    #pragma unroll
    for (int mt = 0; mt < 4; mt++) {
        #pragma unroll
        for (int nt = 0; nt < NT; nt++) {
            int row0 = bm + wm + mt * 16 + (lane >> 2);
            int col  = bn + wn + nt * 8 + (lane & 3) * 2;
            #pragma unroll
            for (int half = 0; half < 2; half++) {
                int row = row0 + half * 8;
                float v0 = acc[mt][nt][half * 2];
                float v1 = acc[mt][nt][half * 2 + 1];
                if (!headN) {
                    size_t base = (size_t)row * N + col;
                    if (BIAS && !ATOMIC) { v0 += bias[col]; v1 += bias[col + 1]; }
                    if (ATOMIC && addBias) { v0 += bias ? bias[col] : 0.f;
                                             v1 += bias ? bias[col + 1] : 0.f; }
                    if (GELU) { v0 = gelu_new(v0); v1 = gelu_new(v1); }
                    if (OUTF32) {
                        float2 o; o.x = v0; o.y = v1;
                        *(float2*)&C[base] = o;
                    }
                    if (OUTH) {
                        *(uint32_t*)&Ch[base] = pack2h(v0, v1);
                    }
                    if (ATOMIC) {
                        atomicAdd(&C[base], v0);
                        atomicAdd(&C[base + 1], v1);
                    }
                } else {
                    size_t rb = (size_t)row * N;
                    if (col < N) {
                        float v = v0;
                        if (BIAS) v += bias[col];
                        C[rb + col] = v;
                    }
                    if (col + 1 < N) {
                        float v = v1;
                        if (BIAS) v += bias[col + 1];
                        C[rb + col + 1] = v;
                    }
                }
            }
        }
    }
}

// ---------------------------------------------------------------------------
// fp16 flash attention (causal), 1-pass, 64-query CTAs, double-buffered K/V,
// 3 CTAs/SM. 128 threads = 4 warps x 16 queries; fp32 softmax.
// ---------------------------------------------------------------------------
#define AROWB 144
#define QBYTES 9216
#define KVSTG  18432
#define SMEM_ATT (QBYTES + 2 * KVSTG)   // 46080

__global__ __launch_bounds__(128, 3) void attn_tc(
    const __half* __restrict__ qkv,
    __half* __restrict__ aout)
{
    extern __shared__ char smem[];
    const uint32_t sb = (uint32_t)__cvta_generic_to_shared(smem);
    const uint32_t sQ = sb;
    const int tid = threadIdx.x, lane = tid & 31, w = tid >> 5;
    const int qt = gridDim.x - 1 - blockIdx.x;     // big tiles first
    const int h = blockIdx.y, b = blockIdx.z;

    #pragma unroll
    for (int i = 0; i < 4; i++) {
        int idx = tid + i * 128;
        int r = idx >> 3, q8 = idx & 7;
        size_t g = ((size_t)(b * Mseq + qt * 64 + r)) * 3072 + h * 192 + q8 * 8;
        cp16(sQ + r * AROWB + q8 * 16, qkv + g);
    }
    cp_commit();

    auto load_kv = [&](int kt, int s) {
        const uint32_t st = sb + QBYTES + s * KVSTG;
        #pragma unroll
        for (int i = 0; i < 4; i++) {
            int idx = tid + i * 128;
            int r = idx >> 3, q8 = idx & 7;
            size_t base = ((size_t)(b * Mseq + kt * 64 + r)) * 3072 + h * 192;
            uint32_t sd = r * AROWB + q8 * 16;
            cp16(st + sd,        qkv + base + 64  + q8 * 8);
            cp16(st + 9216 + sd, qkv + base + 128 + q8 * 8);
        }
        cp_commit();
    };

    const int nkt = qt + 1;
    load_kv(0, 0);
    asm volatile("cp.async.wait_group 1;");
    __syncthreads();

    const int lr  = lane & 15;
    const int khi = (lane >> 4) << 3;

    uint32_t qf[4][4];
    #pragma unroll
    for (int kc = 0; kc < 4; kc++) {
        uint32_t ad = (w * 16 + lr) * AROWB + (kc * 16 + khi) * 2;
        ldsm4(qf[kc][0], qf[kc][1], qf[kc][2], qf[kc][3], sQ + ad);
    }

    float oacc[8][4];
    #pragma unroll
    for (int i = 0; i < 8; i++)
        #pragma unroll
        for (int j = 0; j < 4; j++) oacc[i][j] = 0.f;
    float mA = -1e30f, mB = -1e30f, lA = 0.f, lB = 0.f;

    const int rowA = qt * 64 + w * 16 + (lane >> 2);
    const int rowB = rowA + 8;

    for (int kt = 0; kt < nkt; kt++) {
        const int s = kt & 1;
        if (kt + 1 < nkt) {
            load_kv(kt + 1, s ^ 1);
            asm volatile("cp.async.wait_group 1;");
        } else {
            asm volatile("cp.async.wait_group 0;");
        }
        __syncthreads();

        const uint32_t sK = sb + QBYTES + s * KVSTG;
        const uint32_t sV = sK + 9216;

        float sacc[8][4];
        #pragma unroll
        for (int i = 0; i < 8; i++)
            #pragma unroll
            for (int j = 0; j < 4; j++) sacc[i][j] = 0.f;

        #pragma unroll
        for (int kc = 0; kc < 4; kc++) {
            uint32_t kf[4][4];
            #pragma unroll
            for (int g = 0; g < 4; g++) {
                uint32_t ad = (g * 16 + lr) * AROWB + (kc * 16 + khi) * 2;
                ldsm4(kf[g][0], kf[g][1], kf[g][2], kf[g][3], sK + ad);
            }
            #pragma unroll
            for (int nt = 0; nt < 8; nt++) {
                int g = nt >> 1, hh = nt & 1;
                mma16816(sacc[nt], qf[kc], kf[g][hh], kf[g][2 + hh]);
            }
        }

        float mxA = -1e30f, mxB = -1e30f;
        #pragma unroll
        for (int nt = 0; nt < 8; nt++) {
            int k0 = kt * 64 + nt * 8 + (lane & 3) * 2;
            float s0 = sacc[nt][0] * 0.125f;
            float s1 = sacc[nt][1] * 0.125f;
            float s2 = sacc[nt][2] * 0.125f;
            float s3 = sacc[nt][3] * 0.125f;
            if (k0     > rowA) s0 = -1e30f;
            if (k0 + 1 > rowA) s1 = -1e30f;
            if (k0     > rowB) s2 = -1e30f;
            if (k0 + 1 > rowB) s3 = -1e30f;
            sacc[nt][0] = s0; sacc[nt][1] = s1;
            sacc[nt][2] = s2; sacc[nt][3] = s3;
            mxA = fmaxf(mxA, fmaxf(s0, s1));
            mxB = fmaxf(mxB, fmaxf(s2, s3));
        }
        mxA = fmaxf(mxA, __shfl_xor_sync(0xffffffffu, mxA, 1));
        mxA = fmaxf(mxA, __shfl_xor_sync(0xffffffffu, mxA, 2));
        mxB = fmaxf(mxB, __shfl_xor_sync(0xffffffffu, mxB, 1));
        mxB = fmaxf(mxB, __shfl_xor_sync(0xffffffffu, mxB, 2));
        float mnA = fmaxf(mA, mxA), mnB = fmaxf(mB, mxB);
        float cA = __expf(mA - mnA), cB = __expf(mB - mnB);
        mA = mnA; mB = mnB;

        float sA = 0.f, sB = 0.f;
        #pragma unroll
        for (int nt = 0; nt < 8; nt++) {
            sacc[nt][0] = __expf(sacc[nt][0] - mnA);
            sacc[nt][1] = __expf(sacc[nt][1] - mnA);
            sacc[nt][2] = __expf(sacc[nt][2] - mnB);
            sacc[nt][3] = __expf(sacc[nt][3] - mnB);
            sA += sacc[nt][0] + sacc[nt][1];
            sB += sacc[nt][2] + sacc[nt][3];
        }
        sA += __shfl_xor_sync(0xffffffffu, sA, 1);
        sA += __shfl_xor_sync(0xffffffffu, sA, 2);
        sB += __shfl_xor_sync(0xffffffffu, sB, 1);
        sB += __shfl_xor_sync(0xffffffffu, sB, 2);
        lA = lA * cA + sA;
        lB = lB * cB + sB;
        #pragma unroll
        for (int nt = 0; nt < 8; nt++) {
            oacc[nt][0] *= cA; oacc[nt][1] *= cA;
            oacc[nt][2] *= cB; oacc[nt][3] *= cB;
        }

        #pragma unroll
        for (int kc = 0; kc < 4; kc++) {
            uint32_t ph[4];
            ph[0] = pack2h(sacc[2 * kc][0],     sacc[2 * kc][1]);
            ph[1] = pack2h(sacc[2 * kc][2],     sacc[2 * kc][3]);
            ph[2] = pack2h(sacc[2 * kc + 1][0], sacc[2 * kc + 1][1]);
            ph[3] = pack2h(sacc[2 * kc + 1][2], sacc[2 * kc + 1][3]);

            uint32_t vf[4][4];
            #pragma unroll
            for (int dg = 0; dg < 4; dg++) {
                uint32_t ad = (kc * 16 + (lane & 7) + ((lane >> 4) << 3)) * AROWB
                            + (dg * 16 + ((lane >> 3) & 1) * 8) * 2;
                ldsm4t(vf[dg][0], vf[dg][1], vf[dg][2], vf[dg][3], sV + ad);
            }
            #pragma unroll
            for (int nt = 0; nt < 8; nt++) {
                int dg = nt >> 1, hh = nt & 1;
                mma16816(oacc[nt], ph, vf[dg][hh], vf[dg][hh + 2]);
            }
        }
        __syncthreads();
    }

    float iA = 1.f / lA, iB = 1.f / lB;
    #pragma unroll
    for (int nt = 0; nt < 8; nt++) {
        int col = h * 64 + nt * 8 + (lane & 3) * 2;
        size_t gA = ((size_t)(b * Mseq + rowA)) * Dm + col;
        size_t gB = ((size_t)(b * Mseq + rowB)) * Dm + col;
        *(uint32_t*)&aout[gA] = pack2h(oacc[nt][0] * iA, oacc[nt][1] * iA);
        *(uint32_t*)&aout[gB] = pack2h(oacc[nt][2] * iB, oacc[nt][3] * iB);
    }
}

// ---------------------------------------------------------------------------
// Host launcher
// ---------------------------------------------------------------------------
extern "C" void kernel_launch(void* const* d_in, const int* in_sizes, int n_in,
                              void* d_out, int out_size)
{
    const int*   tokens = (const int*)  d_in[0];
    const float* emb    = (const float*)d_in[1];
    const float* pos    = (const float*)d_in[2];
    const float* ln1_s  = (const float*)d_in[3];
    const float* ln1_b  = (const float*)d_in[4];
    const float* Pi     = (const float*)d_in[5];
    const float* Po     = (const float*)d_in[6];
    const float* ln2_s  = (const float*)d_in[7];
    const float* ln2_b  = (const float*)d_in[8];
    const float* W1     = (const float*)d_in[9];
    const float* b1     = (const float*)d_in[10];
    const float* W2     = (const float*)d_in[11];
    const float* b2     = (const float*)d_in[12];
    const float* lnf_s  = (const float*)d_in[13];
    const float* lnf_b  = (const float*)d_in[14];
    const float* Wh     = (const float*)d_in[15];
    const float* bh     = (const float*)d_in[16];
    float* out = (float*)d_out;
    const int V = in_sizes[16];

    float *x;
    __half *qkv, *y, *a, *hbuf;
    __half *PiTh, *PoTh, *W1Th, *W2Th, *WhTh;
    cudaGetSymbolAddress((void**)&x,    g_x);
    cudaGetSymbolAddress((void**)&qkv,  g_qkv);
    cudaGetSymbolAddress((void**)&y,    g_y);
    cudaGetSymbolAddress((void**)&a,    g_a);
    cudaGetSymbolAddress((void**)&hbuf, g_h);
    cudaGetSymbolAddress((void**)&PiTh, g_PiTh);
    cudaGetSymbolAddress((void**)&PoTh, g_PoTh);
    cudaGetSymbolAddress((void**)&W1Th, g_W1Th);
    cudaGetSymbolAddress((void**)&W2Th, g_W2Th);
    cudaGetSymbolAddress((void**)&WhTh, g_WhTh);

    constexpr int SM_64  = smem_gemm<64>();    // 30720
    constexpr int SM_128 = smem_gemm<128>();   // 40960

    // <BIAS, GELU, OUTF32, OUTH, ATOMIC, BN>
    cudaFuncSetAttribute(gemm_hmma<false, false, false, true,  false, 64>,
                         cudaFuncAttributeMaxDynamicSharedMemorySize, SM_64);
    cudaFuncSetAttribute(gemm_hmma<false, false, false, false, true,  128>,
                         cudaFuncAttributeMaxDynamicSharedMemorySize, SM_128);
    cudaFuncSetAttribute(gemm_hmma<true,  true,  false, true,  false, 128>,
                         cudaFuncAttributeMaxDynamicSharedMemorySize, SM_128);
    cudaFuncSetAttribute(gemm_hmma<true,  false, false, false, true,  128>,
                         cudaFuncAttributeMaxDynamicSharedMemorySize, SM_128);
    cudaFuncSetAttribute(gemm_hmma<true,  false, true,  false, false, 128>,
                         cudaFuncAttributeMaxDynamicSharedMemorySize, SM_128);
    cudaFuncSetAttribute(attn_tc,
                         cudaFuncAttributeMaxDynamicSharedMemorySize, SMEM_ATT);

    convT_kernel<<<dim3(48, 16, Ll), 256>>>(Pi, PiTh, Dm, 3 * Dm,
                                            (size_t)Dm * 3 * Dm, (size_t)3 * Dm * Dm);
    convT_kernel<<<dim3(16, 16, Ll), 256>>>(Po, PoTh, Dm, Dm,
                                            (size_t)Dm * Dm, (size_t)Dm * Dm);
    convT_kernel<<<dim3(64, 16, Ll), 256>>>(W1, W1Th, Dm, 4 * Dm,
                                            (size_t)Dm * 4 * Dm, (size_t)4 * Dm * Dm);
    convT_kernel<<<dim3(16, 64, Ll), 256>>>(W2, W2Th, 4 * Dm, Dm,
                                            (size_t)4 * Dm * Dm, (size_t)4 * Dm * Dm);
    convT_kernel<<<dim3(VPAD / 64, 16, 1), 256>>>(Wh, WhTh, Dm, V, 0, 0);

    embed_kernel<<<NTOK, 256>>>(tokens, emb, pos, x);

    for (int l = 0; l < Ll; l++) {
        ln_kernel<<<NTOK, 256>>>(x, y, ln1_s + l * Dm, ln1_b + l * Dm);
        gemm_hmma<false, false, false, true, false, 64>
            <<<dim3(16, 48), 128, SM_64>>>(
            y, PiTh + (size_t)l * 3 * Dm * Dm, nullptr, nullptr, qkv, 3 * Dm, Dm);
        attn_tc<<<dim3(16, Hh, Bn), 128, SMEM_ATT>>>(qkv, a);
        gemm_hmma<false, false, false, false, true, 128>
            <<<dim3(16, 8, 2), 128, SM_128>>>(
            a, PoTh + (size_t)l * Dm * Dm, nullptr, x, nullptr, Dm, Dm);
        ln_kernel<<<NTOK, 256>>>(x, y, ln2_s + l * Dm, ln2_b + l * Dm);
        gemm_hmma<true, true, false, true, false, 128>
            <<<dim3(16, 32), 128, SM_128>>>(
            y, W1Th + (size_t)l * 4 * Dm * Dm,
            b1 + (size_t)l * 4 * Dm, nullptr, hbuf, 4 * Dm, Dm);
        gemm_hmma<true, false, false, false, true, 128>
            <<<dim3(16, 8, 2), 128, SM_128>>>(
            hbuf, W2Th + (size_t)l * 4 * Dm * Dm,
            b2 + (size_t)l * Dm, x, nullptr, Dm, 4 * Dm);
    }

    ln_kernel<<<NTOK, 256>>>(x, y, lnf_s, lnf_b);
    gemm_hmma<true, false, true, false, false, 128>
        <<<dim3(16, VPAD / 128), 128, SM_128>>>(
        y, WhTh, bh, out, nullptr, V, Dm);
}